// round 13
// baseline (speedup 1.0000x reference)
#include <cuda_runtime.h>
#include <cuda_bf16.h>
#include <cstdint>

#define TOKENS   64
#define IN_F     8192
#define OUT_F    8192
#define QIN      7936
#define OUTL     256

#define MT       128                 // out-features per tile
#define TILES    (OUT_F / MT)        // 64
#define NK16T    (IN_F / 16)         // 512 k16 steps per tile
#define TOTAL    (TILES * NK16T)     // 32768 work units

// device scratch (no allocations allowed)
__device__ int   g_fwd[IN_F];                 // forward column permutation
__device__ uint4 g_bf[NK16T * 8 * 32];        // B frags [k16][n][lane] {b0h,b1h,b0l,b1l}

// ---------------------------------------------------------------------------
// helpers
// ---------------------------------------------------------------------------
__device__ __forceinline__ uint32_t pack_bf16x2(float hi_elem, float lo_elem) {
    uint32_t d;
    asm("cvt.rn.bf16x2.f32 %0, %1, %2;" : "=r"(d) : "f"(hi_elem), "f"(lo_elem));
    return d;
}
// split (v0 -> low half, v1 -> high half) into bf16 hi and residual lo packs
__device__ __forceinline__ void split2(float v0, float v1,
                                       uint32_t& h, uint32_t& l) {
    h = pack_bf16x2(v1, v0);
    float h0 = __uint_as_float(h << 16);
    float h1 = __uint_as_float(h & 0xFFFF0000u);
    l = pack_bf16x2(v1 - h1, v0 - h0);
}
__device__ __forceinline__ void mma_bf16(float* c,
                                         uint32_t a0, uint32_t a1,
                                         uint32_t a2, uint32_t a3,
                                         uint32_t b0, uint32_t b1) {
    asm volatile(
        "mma.sync.aligned.m16n8k16.row.col.f32.bf16.bf16.f32 "
        "{%0,%1,%2,%3}, {%4,%5,%6,%7}, {%8,%9}, {%0,%1,%2,%3};"
        : "+f"(c[0]), "+f"(c[1]), "+f"(c[2]), "+f"(c[3])
        : "r"(a0), "r"(a1), "r"(a2), "r"(a3), "r"(b0), "r"(b1));
}
__device__ __forceinline__ float4 ldg4(const float* p) {
    return __ldg((const float4*)p);
}

// ---------------------------------------------------------------------------
// Kernel 1: forward permutation  g_fwd[inv[j]] = j
// ---------------------------------------------------------------------------
__global__ void fwd_kernel(const int* __restrict__ inv) {
    int j = blockIdx.x * blockDim.x + threadIdx.x;
    if (j < IN_F) g_fwd[inv[j]] = j;
}

// ---------------------------------------------------------------------------
// Kernel 2: init output with bias (accumulation target for RED.ADD)
// ---------------------------------------------------------------------------
__global__ void __launch_bounds__(256)
init_out_kernel(const float* __restrict__ bias, float* __restrict__ out) {
    int i = blockIdx.x * blockDim.x + threadIdx.x;      // float4 index
    int idx = i * 4;
    int o = idx & (OUT_F - 1);
    *(float4*)(out + idx) = *(const float4*)(bias + o);
}

// ---------------------------------------------------------------------------
// Kernel 3: gather permuted input + pack bf16 hi/lo MMA B-fragments.
// k-PERMUTED: physical k 4tg+{0,1} -> frag slots 2tg,2tg+1 (b0),
// physical 4tg+{2,3} -> 2tg+8,2tg+9 (b1). A uses the same mapping.
// ---------------------------------------------------------------------------
__global__ void __launch_bounds__(256)
prep_b_kernel(const float* __restrict__ inp) {
    __shared__ float tile[64][68];
    __shared__ int   jcol[64];
    const int tid = threadIdx.x;
    const int kb  = blockIdx.x * 64;

    if (tid < 64) jcol[tid] = g_fwd[kb + tid];
    __syncthreads();
    {
        const int k = tid >> 2, tq = tid & 3;
        const int j = jcol[k];
        #pragma unroll
        for (int i = 0; i < 16; ++i) {
            int t = tq * 16 + i;
            tile[k][t] = inp[(size_t)t * IN_F + j];
        }
    }
    __syncthreads();

    const int lane = tid & 31, n = tid >> 5;
    const int g = lane >> 2, tg = lane & 3;
    const int t = n * 8 + g;
    #pragma unroll
    for (int k16l = 0; k16l < 4; ++k16l) {
        const int kl = k16l * 16 + tg * 4;
        uint32_t b0h, b0l, b1h, b1l;
        split2(tile[kl][t],     tile[kl + 1][t], b0h, b0l);
        split2(tile[kl + 2][t], tile[kl + 3][t], b1h, b1l);
        g_bf[(size_t)(blockIdx.x * 4 + k16l) * 256 + n * 32 + lane] =
            make_uint4(b0h, b1h, b0l, b1l);
    }
}

// ---------------------------------------------------------------------------
// Kernel 4: persistent fused transform + HMMA GEMM.
// A: direct LDG.128 -> 2-deep register ring (no smem round-trip).
// B: register-prefetched, STS'd per 4-step group, one __syncthreads per group.
// ---------------------------------------------------------------------------
__global__ void __launch_bounds__(256, 2)
linear_kernel(const float* __restrict__ q_w, const float* __restrict__ fp_w,
              const float* __restrict__ alpha, const float* __restrict__ noise,
              float* __restrict__ out) {
    __shared__ uint4 smB[2 * 4 * 256];       // 32 KB: 2 bufs x 4 k16 x 256

    const int tid  = threadIdx.x;
    const int wid  = tid >> 5;
    const int lane = tid & 31;
    const int g    = lane >> 2;
    const int tg   = lane & 3;
    const int mrow = wid * 16 + g;           // rows mrow, mrow+8 within tile

    const int s_begin = (int)(((long long)TOTAL * blockIdx.x) / gridDim.x);
    const int s_end   = (int)(((long long)TOTAL * (blockIdx.x + 1)) / gridDim.x);
    const int i_end   = s_end - s_begin;

    // ---- A register ring: 2 slots x {q0,q1,n0,n1} float4 ----
    float4 a_q0[2], a_q1[2], a_n0[2], a_n1[2];

    #define LDG_A(S_, b_)                                                      \
    {                                                                          \
        const int Sc_ = ((S_) < TOTAL) ? (S_) : (TOTAL - 1);                   \
        const int kb_ = (Sc_ & (NK16T - 1)) * 16;                              \
        const int r0_ = (Sc_ >> 9) * MT + mrow;                                \
        if (kb_ < QIN) {                                                       \
            const float* q_ = q_w   + (size_t)r0_ * QIN + kb_ + tg * 4;        \
            const float* n_ = noise + (size_t)r0_ * QIN + kb_ + tg * 4;        \
            a_q0[b_] = ldg4(q_);                                               \
            a_q1[b_] = ldg4(q_ + (size_t)8 * QIN);                             \
            a_n0[b_] = ldg4(n_);                                               \
            a_n1[b_] = ldg4(n_ + (size_t)8 * QIN);                             \
        } else {                                                               \
            const float* f_ = fp_w + (size_t)r0_ * OUTL + (kb_ - QIN) + tg * 4;\
            a_q0[b_] = ldg4(f_);                                               \
            a_q1[b_] = ldg4(f_ + (size_t)8 * OUTL);                            \
        }                                                                      \
    }

    // ---- B group prefetch / store (unchanged from R11) ----
    uint4 br[4];
    #define LDG_B(j_)                                                          \
    {                                                                          \
        _Pragma("unroll")                                                      \
        for (int u = 0; u < 4; ++u) {                                          \
            int S_ = s_begin + 4 * (j_) + u;                                   \
            if (S_ >= TOTAL) S_ = TOTAL - 1;                                   \
            br[u] = g_bf[(size_t)(S_ & (NK16T - 1)) * 256 + tid];              \
        }                                                                      \
    }
    #define STS_B(buf_)                                                        \
    {                                                                          \
        _Pragma("unroll")                                                      \
        for (int u = 0; u < 4; ++u)                                            \
            smB[(buf_) * 1024 + u * 256 + tid] = br[u];                        \
    }

    float acc[8][4];
    #pragma unroll
    for (int n = 0; n < 8; ++n)
        #pragma unroll
        for (int j = 0; j < 4; ++j) acc[n][j] = 0.0f;

    #define FLUSH(tile_)                                                       \
    {                                                                          \
        const int Rf = (tile_) * MT + mrow;                                    \
        _Pragma("unroll")                                                      \
        for (int n = 0; n < 8; ++n) {                                          \
            const int t = n * 8 + tg * 2;                                      \
            atomicAdd(out + (size_t)t * OUT_F + Rf,           acc[n][0]);      \
            atomicAdd(out + (size_t)(t + 1) * OUT_F + Rf,     acc[n][1]);      \
            atomicAdd(out + (size_t)t * OUT_F + Rf + 8,       acc[n][2]);      \
            atomicAdd(out + (size_t)(t + 1) * OUT_F + Rf + 8, acc[n][3]);      \
        }                                                                      \
    }

    // ---- prologues ----
    LDG_A(s_begin, 0);
    LDG_A(s_begin + 1, 1);
    LDG_B(0); STS_B(0); LDG_B(1);
    __syncthreads();                         // B buf0 visible

    int cur_tile = s_begin >> 9;
    float a0v = alpha[cur_tile * MT + mrow];
    float a1v = alpha[cur_tile * MT + mrow + 8];
    float dh0 = a0v * (0.5f / 7.0f);
    float dh1 = a1v * (0.5f / 7.0f);

    const int G = (i_end + 3) >> 2;
    for (int jg = 0; jg < G; ++jg) {
        if (jg + 1 < G) STS_B((jg + 1) & 1);  // buf consumed in group jg-1: safe
        if (jg + 2 < G) LDG_B(jg + 2);        // refill regs for next group

        #pragma unroll
        for (int u = 0; u < 4; ++u) {
            const int i = 4 * jg + u;
            if (i < i_end) {
                const int S = s_begin + i;
                const int tile = S >> 9;
                if (tile != cur_tile) {
                    FLUSH(cur_tile);
                    #pragma unroll
                    for (int n = 0; n < 8; ++n)
                        #pragma unroll
                        for (int j = 0; j < 4; ++j) acc[n][j] = 0.0f;
                    a0v = alpha[tile * MT + mrow];
                    a1v = alpha[tile * MT + mrow + 8];
                    dh0 = a0v * (0.5f / 7.0f);
                    dh1 = a1v * (0.5f / 7.0f);
                    cur_tile = tile;
                }

                // ---- transform current A from register ring (loaded 2 steps ago)
                const bool isq = ((S & (NK16T - 1)) * 16) < QIN;
                float4 qa = a_q0[u & 1];
                float4 qb = a_q1[u & 1];
                if (isq) {
                    const float4 na = a_n0[u & 1];
                    const float4 nb = a_n1[u & 1];
                    float w[8] = {qa.x, qa.y, qa.z, qa.w, qb.x, qb.y, qb.z, qb.w};
                    const float nn[8] = {na.x, na.y, na.z, na.w,
                                         nb.x, nb.y, nb.z, nb.w};
                    #pragma unroll
                    for (int e = 0; e < 8; ++e) {
                        const float a  = (e < 4) ? a0v : a1v;
                        const float dh = (e < 4) ? dh0 : dh1;
                        float v = w[e];
                        w[e] = (v >= a) ? a : ((v <= -a) ? -a : fmaf(nn[e], dh, v));
                    }
                    qa = make_float4(w[0], w[1], w[2], w[3]);
                    qb = make_float4(w[4], w[5], w[6], w[7]);
                }

                uint32_t ah[4], al[4];
                split2(qa.x, qa.y, ah[0], al[0]);
                split2(qa.z, qa.w, ah[2], al[2]);
                split2(qb.x, qb.y, ah[1], al[1]);
                split2(qb.z, qb.w, ah[3], al[3]);

                // ring slot (u&1) now free -> load step S+2 into it
                LDG_A(S + 2, u & 1);

                // ---- MMA burst; B from smem (interleaves with split/LDG above)
                const uint4* bb = smB + ((size_t)(jg & 1)) * 1024 + u * 256;
                #pragma unroll
                for (int n = 0; n < 8; ++n) {
                    const uint4 bv = bb[n * 32 + lane];
                    mma_bf16(acc[n], ah[0], ah[1], ah[2], ah[3], bv.x, bv.y);
                    mma_bf16(acc[n], ah[0], ah[1], ah[2], ah[3], bv.z, bv.w);
                    mma_bf16(acc[n], al[0], al[1], al[2], al[3], bv.x, bv.y);
                }
            }
        }
        __syncthreads();                      // group done; next B buf visible
    }

    FLUSH(cur_tile);

    #undef LDG_A
    #undef LDG_B
    #undef STS_B
    #undef FLUSH
}

// ---------------------------------------------------------------------------
extern "C" void kernel_launch(void* const* d_in, const int* in_sizes, int n_in,
                              void* d_out, int out_size) {
    const float* input  = (const float*)d_in[0];
    const float* q_w    = (const float*)d_in[1];
    const float* fp_w   = (const float*)d_in[2];
    const float* alpha  = (const float*)d_in[3];
    const float* bias   = (const float*)d_in[4];
    const float* noise  = (const float*)d_in[5];
    const int*   inv    = (const int*)d_in[6];
    float* out = (float*)d_out;
    (void)in_sizes; (void)n_in; (void)out_size;

    static int nsm = 0;
    if (!nsm) {
        cudaDeviceGetAttribute(&nsm, cudaDevAttrMultiProcessorCount, 0);
        if (nsm <= 0) nsm = 148;
    }

    fwd_kernel<<<IN_F / 256, 256>>>(inv);
    init_out_kernel<<<TOKENS * OUT_F / 4 / 256, 256>>>(bias, out);
    prep_b_kernel<<<IN_F / 64, 256>>>(input);
    linear_kernel<<<2 * nsm, 256>>>(q_w, fp_w, alpha, noise, out);
}

// round 14
// speedup vs baseline: 1.0772x; 1.0772x over previous
#include <cuda_runtime.h>
#include <cuda_bf16.h>
#include <cstdint>

#define TOKENS   64
#define IN_F     8192
#define OUT_F    8192
#define QIN      7936
#define OUTL     256

#define MT       128                 // out-features per tile
#define TILES    (OUT_F / MT)        // 64
#define NK16T    (IN_F / 16)         // 512 k16 steps per tile
#define TOTAL    (TILES * NK16T)     // 32768 work units

// device scratch (no allocations allowed)
__device__ int   g_fwd[IN_F];                 // forward column permutation
__device__ uint4 g_bf[NK16T * 8 * 32];        // B frags [k16][n][lane] {b0h,b1h,b0l,b1l}

// ---------------------------------------------------------------------------
// helpers
// ---------------------------------------------------------------------------
__device__ __forceinline__ uint32_t pack_bf16x2(float hi_elem, float lo_elem) {
    uint32_t d;
    asm("cvt.rn.bf16x2.f32 %0, %1, %2;" : "=r"(d) : "f"(hi_elem), "f"(lo_elem));
    return d;
}
// split (v0 -> low half, v1 -> high half) into bf16 hi and residual lo packs
__device__ __forceinline__ void split2(float v0, float v1,
                                       uint32_t& h, uint32_t& l) {
    h = pack_bf16x2(v1, v0);
    float h0 = __uint_as_float(h << 16);
    float h1 = __uint_as_float(h & 0xFFFF0000u);
    l = pack_bf16x2(v1 - h1, v0 - h0);
}
__device__ __forceinline__ void mma_bf16(float* c,
                                         uint32_t a0, uint32_t a1,
                                         uint32_t a2, uint32_t a3,
                                         uint32_t b0, uint32_t b1) {
    asm volatile(
        "mma.sync.aligned.m16n8k16.row.col.f32.bf16.bf16.f32 "
        "{%0,%1,%2,%3}, {%4,%5,%6,%7}, {%8,%9}, {%0,%1,%2,%3};"
        : "+f"(c[0]), "+f"(c[1]), "+f"(c[2]), "+f"(c[3])
        : "r"(a0), "r"(a1), "r"(a2), "r"(a3), "r"(b0), "r"(b1));
}
__device__ __forceinline__ float4 ldg4(const float* p) {
    return __ldg((const float4*)p);
}
__device__ __forceinline__ void cp16(uint32_t dst, const void* src) {
    asm volatile("cp.async.cg.shared.global [%0], [%1], 16;"
                 :: "r"(dst), "l"(src));
}
__device__ __forceinline__ void cp_commit() {
    asm volatile("cp.async.commit_group;" ::: "memory");
}
__device__ __forceinline__ void cp_wait1() {
    asm volatile("cp.async.wait_group 1;" ::: "memory");
}
__device__ __forceinline__ void cp_wait0() {
    asm volatile("cp.async.wait_group 0;" ::: "memory");
}
__device__ __forceinline__ uint32_t smem_u32(const void* p) {
    uint32_t a;
    asm("{ .reg .u64 t; cvta.to.shared.u64 t, %1; cvt.u32.u64 %0, t; }"
        : "=r"(a) : "l"(p));
    return a;
}

// ---------------------------------------------------------------------------
// Kernel 1: forward permutation  g_fwd[inv[j]] = j
// ---------------------------------------------------------------------------
__global__ void fwd_kernel(const int* __restrict__ inv) {
    int j = blockIdx.x * blockDim.x + threadIdx.x;
    if (j < IN_F) g_fwd[inv[j]] = j;
}

// ---------------------------------------------------------------------------
// Kernel 2: init output with bias (accumulation target for RED.ADD)
// ---------------------------------------------------------------------------
__global__ void __launch_bounds__(256)
init_out_kernel(const float* __restrict__ bias, float* __restrict__ out) {
    int i = blockIdx.x * blockDim.x + threadIdx.x;      // float4 index
    int idx = i * 4;
    int o = idx & (OUT_F - 1);
    *(float4*)(out + idx) = *(const float4*)(bias + o);
}

// ---------------------------------------------------------------------------
// Kernel 3: gather permuted input + pack bf16 hi/lo MMA B-fragments.
// k-PERMUTED: physical k 4tg+{0,1} -> frag slots 2tg,2tg+1 (b0),
// physical 4tg+{2,3} -> 2tg+8,2tg+9 (b1). A uses the same mapping.
// ---------------------------------------------------------------------------
__global__ void __launch_bounds__(256)
prep_b_kernel(const float* __restrict__ inp) {
    __shared__ float tile[64][68];
    __shared__ int   jcol[64];
    const int tid = threadIdx.x;
    const int kb  = blockIdx.x * 64;

    if (tid < 64) jcol[tid] = g_fwd[kb + tid];
    __syncthreads();
    {
        const int k = tid >> 2, tq = tid & 3;
        const int j = jcol[k];
        #pragma unroll
        for (int i = 0; i < 16; ++i) {
            int t = tq * 16 + i;
            tile[k][t] = inp[(size_t)t * IN_F + j];
        }
    }
    __syncthreads();

    const int lane = tid & 31, n = tid >> 5;
    const int g = lane >> 2, tg = lane & 3;
    const int t = n * 8 + g;
    #pragma unroll
    for (int k16l = 0; k16l < 4; ++k16l) {
        const int kl = k16l * 16 + tg * 4;
        uint32_t b0h, b0l, b1h, b1l;
        split2(tile[kl][t],     tile[kl + 1][t], b0h, b0l);
        split2(tile[kl + 2][t], tile[kl + 3][t], b1h, b1l);
        g_bf[(size_t)(blockIdx.x * 4 + k16l) * 256 + n * 32 + lane] =
            make_uint4(b0h, b1h, b0l, b1l);
    }
}

// ---------------------------------------------------------------------------
// Kernel 4: persistent fused transform + HMMA GEMM.
// A: direct LDG.128 -> 2-deep register ring (no smem round-trip).
// B: cp.async GMEM->smem, double-buffered per 4-step group (no register staging).
// ---------------------------------------------------------------------------
__global__ void __launch_bounds__(256, 2)
linear_kernel(const float* __restrict__ q_w, const float* __restrict__ fp_w,
              const float* __restrict__ alpha, const float* __restrict__ noise,
              float* __restrict__ out) {
    __shared__ uint4 smB[2 * 4 * 256];       // 32 KB: 2 bufs x 4 k16 x 256
    const uint32_t sbB = smem_u32(smB);

    const int tid  = threadIdx.x;
    const int wid  = tid >> 5;
    const int lane = tid & 31;
    const int g    = lane >> 2;
    const int tg   = lane & 3;
    const int mrow = wid * 16 + g;           // rows mrow, mrow+8 within tile

    const int s_begin = (int)(((long long)TOTAL * blockIdx.x) / gridDim.x);
    const int s_end   = (int)(((long long)TOTAL * (blockIdx.x + 1)) / gridDim.x);
    const int i_end   = s_end - s_begin;

    // ---- A register ring: 2 slots x {q0,q1,n0,n1} float4 ----
    float4 a_q0[2], a_q1[2], a_n0[2], a_n1[2];

    #define LDG_A(S_, b_)                                                      \
    {                                                                          \
        const int Sc_ = ((S_) < TOTAL) ? (S_) : (TOTAL - 1);                   \
        const int kb_ = (Sc_ & (NK16T - 1)) * 16;                              \
        const int r0_ = (Sc_ >> 9) * MT + mrow;                                \
        if (kb_ < QIN) {                                                       \
            const float* q_ = q_w   + (size_t)r0_ * QIN + kb_ + tg * 4;        \
            const float* n_ = noise + (size_t)r0_ * QIN + kb_ + tg * 4;        \
            a_q0[b_] = ldg4(q_);                                               \
            a_q1[b_] = ldg4(q_ + (size_t)8 * QIN);                             \
            a_n0[b_] = ldg4(n_);                                               \
            a_n1[b_] = ldg4(n_ + (size_t)8 * QIN);                             \
        } else {                                                               \
            const float* f_ = fp_w + (size_t)r0_ * OUTL + (kb_ - QIN) + tg * 4;\
            a_q0[b_] = ldg4(f_);                                               \
            a_q1[b_] = ldg4(f_ + (size_t)8 * OUTL);                            \
        }                                                                      \
    }

    // ---- B group issue: 4 steps of fragments via cp.async, one commit ----
    #define ISSUE_B(j_)                                                        \
    {                                                                          \
        _Pragma("unroll")                                                      \
        for (int u = 0; u < 4; ++u) {                                          \
            int S_ = s_begin + 4 * (j_) + u;                                   \
            if (S_ >= TOTAL) S_ = TOTAL - 1;                                   \
            cp16(sbB + (uint32_t)(((((j_) & 1) * 1024) + u * 256 + tid) * 16), \
                 g_bf + (size_t)(S_ & (NK16T - 1)) * 256 + tid);               \
        }                                                                      \
        cp_commit();                                                           \
    }

    float acc[8][4];
    #pragma unroll
    for (int n = 0; n < 8; ++n)
        #pragma unroll
        for (int j = 0; j < 4; ++j) acc[n][j] = 0.0f;

    #define FLUSH(tile_)                                                       \
    {                                                                          \
        const int Rf = (tile_) * MT + mrow;                                    \
        _Pragma("unroll")                                                      \
        for (int n = 0; n < 8; ++n) {                                          \
            const int t = n * 8 + tg * 2;                                      \
            atomicAdd(out + (size_t)t * OUT_F + Rf,           acc[n][0]);      \
            atomicAdd(out + (size_t)(t + 1) * OUT_F + Rf,     acc[n][1]);      \
            atomicAdd(out + (size_t)t * OUT_F + Rf + 8,       acc[n][2]);      \
            atomicAdd(out + (size_t)(t + 1) * OUT_F + Rf + 8, acc[n][3]);      \
        }                                                                      \
    }

    // ---- prologues ----
    LDG_A(s_begin, 0);
    LDG_A(s_begin + 1, 1);
    ISSUE_B(0);
    ISSUE_B(1);
    cp_wait1();                              // buf0 landed
    __syncthreads();                         // visible to all warps

    int cur_tile = s_begin >> 9;
    float a0v = alpha[cur_tile * MT + mrow];
    float a1v = alpha[cur_tile * MT + mrow + 8];
    float dh0 = a0v * (0.5f / 7.0f);
    float dh1 = a1v * (0.5f / 7.0f);

    const int G = (i_end + 3) >> 2;
    for (int jg = 0; jg < G; ++jg) {
        #pragma unroll
        for (int u = 0; u < 4; ++u) {
            const int i = 4 * jg + u;
            if (i < i_end) {
                const int S = s_begin + i;
                const int tile = S >> 9;
                if (tile != cur_tile) {
                    FLUSH(cur_tile);
                    #pragma unroll
                    for (int n = 0; n < 8; ++n)
                        #pragma unroll
                        for (int j = 0; j < 4; ++j) acc[n][j] = 0.0f;
                    a0v = alpha[tile * MT + mrow];
                    a1v = alpha[tile * MT + mrow + 8];
                    dh0 = a0v * (0.5f / 7.0f);
                    dh1 = a1v * (0.5f / 7.0f);
                    cur_tile = tile;
                }

                // ---- transform current A from register ring (loaded 2 steps ago)
                const bool isq = ((S & (NK16T - 1)) * 16) < QIN;
                float4 qa = a_q0[u & 1];
                float4 qb = a_q1[u & 1];
                if (isq) {
                    const float4 na = a_n0[u & 1];
                    const float4 nb = a_n1[u & 1];
                    float w[8] = {qa.x, qa.y, qa.z, qa.w, qb.x, qb.y, qb.z, qb.w};
                    const float nn[8] = {na.x, na.y, na.z, na.w,
                                         nb.x, nb.y, nb.z, nb.w};
                    #pragma unroll
                    for (int e = 0; e < 8; ++e) {
                        const float a  = (e < 4) ? a0v : a1v;
                        const float dh = (e < 4) ? dh0 : dh1;
                        float v = w[e];
                        w[e] = (v >= a) ? a : ((v <= -a) ? -a : fmaf(nn[e], dh, v));
                    }
                    qa = make_float4(w[0], w[1], w[2], w[3]);
                    qb = make_float4(w[4], w[5], w[6], w[7]);
                }

                uint32_t ah[4], al[4];
                split2(qa.x, qa.y, ah[0], al[0]);
                split2(qa.z, qa.w, ah[2], al[2]);
                split2(qb.x, qb.y, ah[1], al[1]);
                split2(qb.z, qb.w, ah[3], al[3]);

                // ring slot (u&1) now free -> load step S+2 into it
                LDG_A(S + 2, u & 1);

                // ---- MMA burst; B from smem (interleaves with split/LDG above)
                const uint4* bb = smB + ((size_t)(jg & 1)) * 1024 + u * 256;
                #pragma unroll
                for (int n = 0; n < 8; ++n) {
                    const uint4 bv = bb[n * 32 + lane];
                    mma_bf16(acc[n], ah[0], ah[1], ah[2], ah[3], bv.x, bv.y);
                    mma_bf16(acc[n], ah[0], ah[1], ah[2], ah[3], bv.z, bv.w);
                    mma_bf16(acc[n], al[0], al[1], al[2], al[3], bv.x, bv.y);
                }
            }
        }

        // ---- group boundary: refill the just-consumed B buffer ----
        __syncthreads();                     // all warps done reading buf(jg&1)
        if (jg + 2 < G) {
            ISSUE_B(jg + 2);                 // -> buf(jg&1)
            cp_wait1();                      // own buf((jg+1)&1) complete
        } else {
            cp_wait0();                      // drain: next buf fully complete
        }
        __syncthreads();                     // others' cp.async visible
    }

    FLUSH(cur_tile);

    #undef LDG_A
    #undef ISSUE_B
    #undef FLUSH
}

// ---------------------------------------------------------------------------
extern "C" void kernel_launch(void* const* d_in, const int* in_sizes, int n_in,
                              void* d_out, int out_size) {
    const float* input  = (const float*)d_in[0];
    const float* q_w    = (const float*)d_in[1];
    const float* fp_w   = (const float*)d_in[2];
    const float* alpha  = (const float*)d_in[3];
    const float* bias   = (const float*)d_in[4];
    const float* noise  = (const float*)d_in[5];
    const int*   inv    = (const int*)d_in[6];
    float* out = (float*)d_out;
    (void)in_sizes; (void)n_in; (void)out_size;

    static int nsm = 0;
    if (!nsm) {
        cudaDeviceGetAttribute(&nsm, cudaDevAttrMultiProcessorCount, 0);
        if (nsm <= 0) nsm = 148;
    }

    fwd_kernel<<<IN_F / 256, 256>>>(inv);
    init_out_kernel<<<TOKENS * OUT_F / 4 / 256, 256>>>(bias, out);
    prep_b_kernel<<<IN_F / 64, 256>>>(input);
    linear_kernel<<<2 * nsm, 256>>>(q_w, fp_w, alpha, noise, out);
}

// round 17
// speedup vs baseline: 1.1443x; 1.0623x over previous
#include <cuda_runtime.h>
#include <cuda_bf16.h>
#include <cstdint>

#define TOKENS   64
#define IN_F     8192
#define OUT_F    8192
#define QIN      7936
#define OUTL     256

#define MT       128                 // out-features per tile
#define TILES    (OUT_F / MT)        // 64
#define NK16T    (IN_F / 16)         // 512 k16 steps per tile
#define TOTAL    (TILES * NK16T)     // 32768 work units

#define A_RING_F   (4 * 8 * 512)     // 4 slots x 8 warps x (256 q + 256 n) = 64 KB
#define B_RING_U4  (2 * 4 * 256)     // 2 bufs x 4 k16 x 256 uint4 = 32 KB
#define SMEM_BYTES (A_RING_F * 4 + B_RING_U4 * 16)   // 98304

// device scratch (no allocations allowed)
__device__ int   g_fwd[IN_F];                 // forward column permutation
__device__ uint4 g_bf[NK16T * 8 * 32];        // B frags [k16][n][lane] {b0h,b1h,b0l,b1l}

// ---------------------------------------------------------------------------
// helpers
// ---------------------------------------------------------------------------
__device__ __forceinline__ uint32_t pack_bf16x2(float hi_elem, float lo_elem) {
    uint32_t d;
    asm("cvt.rn.bf16x2.f32 %0, %1, %2;" : "=r"(d) : "f"(hi_elem), "f"(lo_elem));
    return d;
}
// split (v0 -> low half, v1 -> high half) into bf16 hi and residual lo packs
__device__ __forceinline__ void split2(float v0, float v1,
                                       uint32_t& h, uint32_t& l) {
    h = pack_bf16x2(v1, v0);
    float h0 = __uint_as_float(h << 16);
    float h1 = __uint_as_float(h & 0xFFFF0000u);
    l = pack_bf16x2(v1 - h1, v0 - h0);
}
__device__ __forceinline__ void mma_bf16(float* c,
                                         uint32_t a0, uint32_t a1,
                                         uint32_t a2, uint32_t a3,
                                         uint32_t b0, uint32_t b1) {
    asm volatile(
        "mma.sync.aligned.m16n8k16.row.col.f32.bf16.bf16.f32 "
        "{%0,%1,%2,%3}, {%4,%5,%6,%7}, {%8,%9}, {%0,%1,%2,%3};"
        : "+f"(c[0]), "+f"(c[1]), "+f"(c[2]), "+f"(c[3])
        : "r"(a0), "r"(a1), "r"(a2), "r"(a3), "r"(b0), "r"(b1));
}
__device__ __forceinline__ void cp16(uint32_t dst, const void* src) {
    asm volatile("cp.async.cg.shared.global [%0], [%1], 16;"
                 :: "r"(dst), "l"(src));
}
__device__ __forceinline__ void cp_commit() {
    asm volatile("cp.async.commit_group;" ::: "memory");
}
__device__ __forceinline__ void cp_wait1() {
    asm volatile("cp.async.wait_group 1;" ::: "memory");
}
__device__ __forceinline__ void cp_wait0() {
    asm volatile("cp.async.wait_group 0;" ::: "memory");
}
__device__ __forceinline__ uint32_t smem_u32(const void* p) {
    uint32_t a;
    asm("{ .reg .u64 t; cvta.to.shared.u64 t, %1; cvt.u32.u64 %0, t; }"
        : "=r"(a) : "l"(p));
    return a;
}

// ---------------------------------------------------------------------------
// Kernel 1: forward permutation  g_fwd[inv[j]] = j
// ---------------------------------------------------------------------------
__global__ void fwd_kernel(const int* __restrict__ inv) {
    int j = blockIdx.x * blockDim.x + threadIdx.x;
    if (j < IN_F) g_fwd[inv[j]] = j;
}

// ---------------------------------------------------------------------------
// Kernel 2: init output with bias (accumulation target for RED.ADD)
// ---------------------------------------------------------------------------
__global__ void __launch_bounds__(256)
init_out_kernel(const float* __restrict__ bias, float* __restrict__ out) {
    int i = blockIdx.x * blockDim.x + threadIdx.x;      // float4 index
    int idx = i * 4;
    int o = idx & (OUT_F - 1);
    *(float4*)(out + idx) = *(const float4*)(bias + o);
}

// ---------------------------------------------------------------------------
// Kernel 3: gather permuted input + pack bf16 hi/lo MMA B-fragments.
// k-PERMUTED: physical k 4tg+{0,1} -> frag slots 2tg,2tg+1 (b0),
// physical 4tg+{2,3} -> 2tg+8,2tg+9 (b1). A uses the same mapping.
// ---------------------------------------------------------------------------
__global__ void __launch_bounds__(256)
prep_b_kernel(const float* __restrict__ inp) {
    __shared__ float tile[64][68];
    __shared__ int   jcol[64];
    const int tid = threadIdx.x;
    const int kb  = blockIdx.x * 64;

    if (tid < 64) jcol[tid] = g_fwd[kb + tid];
    __syncthreads();
    {
        const int k = tid >> 2, tq = tid & 3;
        const int j = jcol[k];
        #pragma unroll
        for (int i = 0; i < 16; ++i) {
            int t = tq * 16 + i;
            tile[k][t] = inp[(size_t)t * IN_F + j];
        }
    }
    __syncthreads();

    const int lane = tid & 31, n = tid >> 5;
    const int g = lane >> 2, tg = lane & 3;
    const int t = n * 8 + g;
    #pragma unroll
    for (int k16l = 0; k16l < 4; ++k16l) {
        const int kl = k16l * 16 + tg * 4;
        uint32_t b0h, b0l, b1h, b1l;
        split2(tile[kl][t],     tile[kl + 1][t], b0h, b0l);
        split2(tile[kl + 2][t], tile[kl + 3][t], b1h, b1l);
        g_bf[(size_t)(blockIdx.x * 4 + k16l) * 256 + n * 32 + lane] =
            make_uint4(b0h, b1h, b0l, b1l);
    }
}

// ---------------------------------------------------------------------------
// Kernel 4: persistent fused transform + HMMA GEMM, SPLIT-AHEAD pipeline.
// Step i: MMA(i) from frag ring fr[i&1] (built last step), while
// transform+split(i+1) builds fr[(i+1)&1] — independent, interleavable.
// RACE-FIXED vs R15: A ring 4-deep with issue(i+4) so wait_group 1 covers
// stage i+2 (SPLIT needs i+1, margin 1); B chunk 3 issued at u==2 so the
// whole next B group is covered by the wait at the u==0 barrier.
// ---------------------------------------------------------------------------
__global__ void __launch_bounds__(256, 2)
linear_kernel(const float* __restrict__ q_w, const float* __restrict__ fp_w,
              const float* __restrict__ alpha, const float* __restrict__ noise,
              float* __restrict__ out) {
    extern __shared__ char smraw[];
    float* smA = (float*)smraw;
    uint4* smB = (uint4*)(smraw + A_RING_F * 4);
    const uint32_t sbA = smem_u32(smA);
    const uint32_t sbB = smem_u32(smB);

    const int tid  = threadIdx.x;
    const int wid  = tid >> 5;
    const int lane = tid & 31;
    const int g    = lane >> 2;
    const int tg   = lane & 3;
    const int mrow = wid * 16 + g;           // rows mrow, mrow+8 within tile
    const int ar   = lane >> 1;              // A staging: row 0..15 of own warp
    const int ahh  = lane & 1;               // A staging: 32B half

    const int s_begin = (int)(((long long)TOTAL * blockIdx.x) / gridDim.x);
    const int s_end   = (int)(((long long)TOTAL * (blockIdx.x + 1)) / gridDim.x);
    const int i_end   = s_end - s_begin;

    // ---- A stage issue (per warp; NO commit inside); slot = stage & 3 ----
    #define ISSUE_A(T_)                                                        \
    {                                                                          \
        const int Sc_ = (s_begin + (T_) < TOTAL) ? s_begin + (T_) : TOTAL - 1; \
        const int slot_ = (T_) & 3;                                            \
        const uint32_t d_ = sbA + (uint32_t)(((slot_ * 8 + wid) * 512 +        \
                            ar * 16 + ahh * 8) * 4);                           \
        const int kb_  = (Sc_ & (NK16T - 1)) * 16;                             \
        const int row_ = (Sc_ >> 9) * MT + wid * 16 + ar;                      \
        if (kb_ < QIN) {                                                       \
            const float* q_ = q_w   + (size_t)row_ * QIN + kb_ + ahh * 8;      \
            const float* n_ = noise + (size_t)row_ * QIN + kb_ + ahh * 8;      \
            cp16(d_, q_);        cp16(d_ + 16, q_ + 4);                        \
            cp16(d_ + 1024, n_); cp16(d_ + 1040, n_ + 4);                      \
        } else {                                                               \
            const float* f_ = fp_w + (size_t)row_ * OUTL + (kb_ - QIN) + ahh * 8;\
            cp16(d_, f_);        cp16(d_ + 16, f_ + 4);                        \
        }                                                                      \
    }

    // ---- B chunk issue: chunk u_ of step-group jgp_ (NO commit inside) ----
    #define ISSUE_B(jgp_, u_)                                                  \
    {                                                                          \
        int S_ = s_begin + 4 * (jgp_) + (u_);                                  \
        if (S_ >= TOTAL) S_ = TOTAL - 1;                                       \
        cp16(sbB + (uint32_t)(((((jgp_) & 1) * 1024) + (u_) * 256 + tid) * 16),\
             g_bf + (size_t)(S_ & (NK16T - 1)) * 256 + tid);                   \
    }

    // ---- fragment ring + split-side alpha tracking ----
    uint32_t fr_h[2][4], fr_l[2][4];
    int   sp_tile = -1;
    float a0s = 0.f, a1s = 0.f, dh0s = 0.f, dh1s = 0.f;

    #define SPLIT(T_)                                                          \
    {                                                                          \
        const int Sc_ = (s_begin + (T_) < TOTAL) ? s_begin + (T_) : TOTAL - 1; \
        const int slot_ = (T_) & 3;                                            \
        const int fslot_ = (T_) & 1;                                           \
        const float* st_ = smA + (size_t)(slot_ * 8 + wid) * 512;              \
        const int stile_ = Sc_ >> 9;                                           \
        if (stile_ != sp_tile) {                                               \
            sp_tile = stile_;                                                  \
            a0s = __ldg(alpha + stile_ * MT + mrow);                           \
            a1s = __ldg(alpha + stile_ * MT + mrow + 8);                       \
            dh0s = a0s * (0.5f / 7.0f);                                        \
            dh1s = a1s * (0.5f / 7.0f);                                        \
        }                                                                      \
        const bool isq_ = ((Sc_ & (NK16T - 1)) * 16) < QIN;                    \
        float4 qa_ = *(const float4*)(st_ + g * 16 + tg * 4);                  \
        float4 qb_ = *(const float4*)(st_ + (g + 8) * 16 + tg * 4);            \
        if (isq_) {                                                            \
            const float4 na_ = *(const float4*)(st_ + 256 + g * 16 + tg * 4);  \
            const float4 nb_ = *(const float4*)(st_ + 256 + (g + 8) * 16 + tg * 4);\
            float w_[8] = {qa_.x, qa_.y, qa_.z, qa_.w,                         \
                           qb_.x, qb_.y, qb_.z, qb_.w};                        \
            const float nn_[8] = {na_.x, na_.y, na_.z, na_.w,                  \
                                  nb_.x, nb_.y, nb_.z, nb_.w};                 \
            _Pragma("unroll")                                                  \
            for (int e = 0; e < 8; ++e) {                                      \
                const float a_  = (e < 4) ? a0s : a1s;                         \
                const float dh_ = (e < 4) ? dh0s : dh1s;                       \
                float v_ = w_[e];                                              \
                w_[e] = (v_ >= a_) ? a_ : ((v_ <= -a_) ? -a_                   \
                                            : fmaf(nn_[e], dh_, v_));          \
            }                                                                  \
            qa_ = make_float4(w_[0], w_[1], w_[2], w_[3]);                     \
            qb_ = make_float4(w_[4], w_[5], w_[6], w_[7]);                     \
        }                                                                      \
        split2(qa_.x, qa_.y, fr_h[fslot_][0], fr_l[fslot_][0]);                \
        split2(qa_.z, qa_.w, fr_h[fslot_][2], fr_l[fslot_][2]);                \
        split2(qb_.x, qb_.y, fr_h[fslot_][1], fr_l[fslot_][1]);                \
        split2(qb_.z, qb_.w, fr_h[fslot_][3], fr_l[fslot_][3]);                \
    }

    float acc[8][4];
    #pragma unroll
    for (int n = 0; n < 8; ++n)
        #pragma unroll
        for (int j = 0; j < 4; ++j) acc[n][j] = 0.0f;

    #define FLUSH(tile_)                                                       \
    {                                                                          \
        const int Rf = (tile_) * MT + mrow;                                    \
        _Pragma("unroll")                                                      \
        for (int n = 0; n < 8; ++n) {                                          \
            const int t = n * 8 + tg * 2;                                      \
            atomicAdd(out + (size_t)t * OUT_F + Rf,           acc[n][0]);      \
            atomicAdd(out + (size_t)(t + 1) * OUT_F + Rf,     acc[n][1]);      \
            atomicAdd(out + (size_t)t * OUT_F + Rf + 8,       acc[n][2]);      \
            atomicAdd(out + (size_t)(t + 1) * OUT_F + Rf + 8, acc[n][3]);      \
        }                                                                      \
    }

    // ---- prologue: G0{A0,A1,Bgrp0} G1{A2} G2{A3}; drain; split(0) ----
    ISSUE_A(0);
    ISSUE_A(1);
    ISSUE_B(0, 0); ISSUE_B(0, 1); ISSUE_B(0, 2); ISSUE_B(0, 3);
    cp_commit();
    ISSUE_A(2);
    cp_commit();
    ISSUE_A(3);
    cp_commit();
    cp_wait0();
    __syncthreads();
    SPLIT(0);

    int cur_tile = s_begin >> 9;

    // Steady state at step i: committed = 3 + i groups; wait_group 1 =>
    // complete through step i-2's group => A stages <= i+2 landed, and all
    // B chunks of the group entered at u==0 landed (chunk 3 issued at u==2).
    const int G = (i_end + 3) >> 2;
    for (int jg = 0; jg < G; ++jg) {
        #pragma unroll
        for (int u = 0; u < 4; ++u) {
            const int i = 4 * jg + u;
            cp_wait1();
            if (u == 0) __syncthreads();      // B group jg visible; buf WAR fence

            if (i < i_end) {
                // one commit group per step: A(i+4) + B chunk(s) of group jg+1
                ISSUE_A(i + 4);
                if (u == 0)      { ISSUE_B(jg + 1, 0); }
                else if (u == 1) { ISSUE_B(jg + 1, 1); }
                else if (u == 2) { ISSUE_B(jg + 1, 2); ISSUE_B(jg + 1, 3); }
                cp_commit();

                const int S = s_begin + i;
                const int tile = S >> 9;
                if (tile != cur_tile) {
                    FLUSH(cur_tile);
                    #pragma unroll
                    for (int n = 0; n < 8; ++n)
                        #pragma unroll
                        for (int j = 0; j < 4; ++j) acc[n][j] = 0.0f;
                    cur_tile = tile;
                }

                // ---- independent halves: split(i+1) builds fr[(i+1)&1],
                //      MMA(i) consumes fr[i&1] — scheduler interleaves ----
                SPLIT(i + 1);

                const uint4* bb = smB + ((size_t)(jg & 1)) * 1024 + u * 256;
                #pragma unroll
                for (int n = 0; n < 8; ++n) {
                    const uint4 bv = bb[n * 32 + lane];
                    mma_bf16(acc[n], fr_h[u & 1][0], fr_h[u & 1][1],
                                     fr_h[u & 1][2], fr_h[u & 1][3], bv.x, bv.y);
                    mma_bf16(acc[n], fr_h[u & 1][0], fr_h[u & 1][1],
                                     fr_h[u & 1][2], fr_h[u & 1][3], bv.z, bv.w);
                    mma_bf16(acc[n], fr_l[u & 1][0], fr_l[u & 1][1],
                                     fr_l[u & 1][2], fr_l[u & 1][3], bv.x, bv.y);
                }
            } else {
                cp_commit();                  // keep FIFO periodic in tail
            }
        }
    }

    FLUSH(cur_tile);

    #undef ISSUE_A
    #undef ISSUE_B
    #undef SPLIT
    #undef FLUSH
}

// ---------------------------------------------------------------------------
extern "C" void kernel_launch(void* const* d_in, const int* in_sizes, int n_in,
                              void* d_out, int out_size) {
    const float* input  = (const float*)d_in[0];
    const float* q_w    = (const float*)d_in[1];
    const float* fp_w   = (const float*)d_in[2];
    const float* alpha  = (const float*)d_in[3];
    const float* bias   = (const float*)d_in[4];
    const float* noise  = (const float*)d_in[5];
    const int*   inv    = (const int*)d_in[6];
    float* out = (float*)d_out;
    (void)in_sizes; (void)n_in; (void)out_size;

    static int nsm = 0;
    if (!nsm) {
        cudaDeviceGetAttribute(&nsm, cudaDevAttrMultiProcessorCount, 0);
        if (nsm <= 0) nsm = 148;
        cudaFuncSetAttribute(linear_kernel,
                             cudaFuncAttributeMaxDynamicSharedMemorySize,
                             SMEM_BYTES);
    }

    fwd_kernel<<<IN_F / 256, 256>>>(inv);
    init_out_kernel<<<TOKENS * OUT_F / 4 / 256, 256>>>(bias, out);
    prep_b_kernel<<<IN_F / 64, 256>>>(input);
    linear_kernel<<<2 * nsm, 256, SMEM_BYTES>>>(q_w, fp_w, alpha, noise, out);
}